// round 11
// baseline (speedup 1.0000x reference)
#include <cuda_runtime.h>
#include <stdint.h>

#define NTOT  (8*32*32*9)   // 73728
#define KSEL  512
#define HF_   32
#define WF_   32
#define CCH   1024
#define FEAT  256
#define OUTC  84
#define SS_   14
#define NSAMP 196
#define DET_THRC 0.7f
#define NMS_IOUC 0.7f
#define NBINS 4096
#define NKC   16                // K chunks in gemm1 (64 c each)
#define GRP   16                // rois per gemm1 group
#define NGRP  (KSEL/GRP)        // 32
#define NQ    4                 // pixel quarters in gather

typedef unsigned long long ull;

// ---------------- device scratch (static globals; zero-initialized) ---------
__device__ uint64_t g_cand[NTOT];
__device__ int      g_cand_count;                 // reset by select phase
__device__ __align__(16) int g_hist[NBINS];       // reset by select phase
__device__ int      g_fdone;                      // reset by select phase
__device__ int      g_valid[KSEL];
__device__ int      g_assign[KSEL];
__device__ float    g_rois[KSEL*4];
__device__ float    g_shifted[KSEL*4];
__device__ unsigned g_sup[KSEL*16];
__device__ unsigned g_supany[16];                 // reset by resolver
__device__ int      g_keep[KSEL];
__device__ int      g_done;                       // reset by resolver
__device__ __align__(16) float g_poolT[NQ*KSEL*CCH];    // [q][grp][c][k%16]
__device__ __align__(16) float g_part[NKC*KSEL*FEAT];   // [kc][roi][col]

// ====== fused filter (72 x 1024) + last-block top-K select ==================
__global__ void __launch_bounds__(1024) k_filtersel(const float* __restrict__ pred,
                                                    const float* __restrict__ rois,
                                                    const float* __restrict__ anchors,
                                                    const int*   __restrict__ assign) {
    __shared__ int s_last;
    int tid = threadIdx.x;
    {
        int i = blockIdx.x * 1024 + tid;
        float s = pred[i];
        bool c = (s > DET_THRC);
        unsigned m = __ballot_sync(0xffffffffu, c);
        int n = __popc(m);
        int base = 0;
        if ((tid & 31) == 0 && n)
            base = atomicAdd(&g_cand_count, n);
        base = __shfl_sync(0xffffffffu, base, 0);
        if (c) {
            int r = __popc(m & ((1u << (tid & 31)) - 1u));
            unsigned u = __float_as_uint(s); // s > 0 -> monotone as unsigned
            g_cand[base + r] = ((uint64_t)u << 32) | (unsigned)(0xFFFFFFFFu - (unsigned)i);
            atomicAdd(&g_hist[u >> 19], 1);
        }
    }
    __threadfence();
    __syncthreads();
    if (tid == 0) s_last = (atomicAdd(&g_fdone, 1) == 71) ? 1 : 0;
    __syncthreads();
    if (!s_last) return;
    __threadfence();

    // ---------------- select phase (single block, 1024 threads) -------------
    __shared__ int      sh_hist[NBINS];
    __shared__ int      sh_chunk[1024];
    __shared__ int      sh_warp[32];
    __shared__ unsigned sh_T;
    __shared__ int      sh_cnt;
    __shared__ uint64_t sh_keys[1024];
    int lane = tid & 31, wid = tid >> 5;

    int M = g_cand_count; if (M > NTOT) M = NTOT;
    __syncthreads();
    if (tid == 0) { g_cand_count = 0; sh_cnt = 0; g_fdone = 0; }

    int4 h = ((const int4*)g_hist)[tid];
    ((int4*)g_hist)[tid] = make_int4(0, 0, 0, 0);
    sh_hist[tid*4+0] = h.x; sh_hist[tid*4+1] = h.y;
    sh_hist[tid*4+2] = h.z; sh_hist[tid*4+3] = h.w;
    int csum = h.x + h.y + h.z + h.w;
    sh_chunk[tid] = csum;
    int ws = csum;
    #pragma unroll
    for (int off = 16; off > 0; off >>= 1) ws += __shfl_down_sync(0xffffffffu, ws, off);
    if (lane == 0) sh_warp[wid] = ws;
    __syncthreads();

    if (tid == 0) {
        unsigned T = 1u;
        int cum = 0; int w;
        bool found = false;
        for (w = 31; w >= 0; w--) {
            if (cum + sh_warp[w] >= KSEL) { found = true; break; }
            cum += sh_warp[w];
        }
        if (found) {
            int c;
            for (c = 31; c >= 0; c--) {
                int t = sh_chunk[w*32 + c];
                if (cum + t >= KSEL) break;
                cum += t;
            }
            int base = (w*32 + c) * 4;
            int b;
            for (b = 3; b >= 0; b--) {
                int t = sh_hist[base + b];
                if (cum + t >= KSEL) break;
                cum += t;
            }
            T = (unsigned)(base + b) << 19;
        }
        sh_T = T;
    }
    __syncthreads();
    unsigned T = sh_T;

    for (int j = tid; j < M; j += 1024) {
        uint64_t k = g_cand[j];
        if ((unsigned)(k >> 32) >= T) {
            int p = atomicAdd(&sh_cnt, 1);
            if (p < 1024) sh_keys[p] = k;
        }
    }
    __syncthreads();
    int cnt = sh_cnt; if (cnt > 1024) cnt = 1024;
    if (tid >= cnt) sh_keys[tid] = 0ull;
    __syncthreads();

    // hybrid bitonic sort (descending)
    uint64_t v = sh_keys[tid];
    #pragma unroll
    for (int size = 2; size <= 32; size <<= 1) {
        #pragma unroll
        for (int stride = size >> 1; stride >= 1; stride >>= 1) {
            uint64_t o = __shfl_xor_sync(0xffffffffu, v, stride);
            bool lower = (tid & stride) == 0;
            bool desc  = (tid & size) == 0;
            uint64_t mx = v > o ? v : o, mn = v > o ? o : v;
            v = (desc == lower) ? mx : mn;
        }
    }
    sh_keys[tid] = v;
    __syncthreads();
    for (int size = 64; size <= 1024; size <<= 1) {
        for (int stride = size >> 1; stride >= 32; stride >>= 1) {
            int j = tid ^ stride;
            if (j > tid) {
                uint64_t a = sh_keys[tid], b = sh_keys[j];
                bool desc = (tid & size) == 0;
                if (desc ? (a < b) : (a > b)) { sh_keys[tid] = b; sh_keys[j] = a; }
            }
            __syncthreads();
        }
        v = sh_keys[tid];
        #pragma unroll
        for (int stride = 16; stride >= 1; stride >>= 1) {
            uint64_t o = __shfl_xor_sync(0xffffffffu, v, stride);
            bool lower = (tid & stride) == 0;
            bool desc  = (tid & size) == 0;
            uint64_t mx = v > o ? v : o, mn = v > o ? o : v;
            v = (desc == lower) ? mx : mn;
        }
        sh_keys[tid] = v;
        __syncthreads();
    }

    if (tid < KSEL) {
        uint64_t k = sh_keys[tid];
        unsigned u = (unsigned)(k >> 32);
        int idx = 0, vv = 0;
        if (u != 0u) { idx = (int)(0xFFFFFFFFu - (unsigned)(k & 0xFFFFFFFFu)); vv = 1; }
        g_valid[tid] = vv;
        int a = assign[idx];
        g_assign[tid] = a;
        float fa = (float)a * 1024.0f;
        #pragma unroll
        for (int c = 0; c < 4; c++) g_rois[tid*4 + c] = rois[idx*4 + c];
        float cy = anchors[idx*4+0], cx = anchors[idx*4+1];
        float hh = anchors[idx*4+2], ww = anchors[idx*4+3];
        g_shifted[tid*4+0] = cy - hh*0.5f + fa;
        g_shifted[tid*4+1] = cx - ww*0.5f + fa;
        g_shifted[tid*4+2] = cy + hh*0.5f + fa;
        g_shifted[tid*4+3] = cx + ww*0.5f + fa;
    }
}

// === gatherall: (512 rois x 4 px-quarters) x 256 thr ========================
// per block: rebuild pixel weight list (DETERMINISTIC ballot compaction so all
// 4 quarter-blocks agree); q==0 also emits sup words; gather quarter of pixels
// over all 1024 channels; last of 2048 resolves NMS.
__global__ void __launch_bounds__(256) k_gatherall(const float* __restrict__ feats) {
    __shared__ float4   sb[KSEL];          // 8KB boxes (q==0 sup + resolve reuse)
    __shared__ unsigned sbig[KSEL*16];     // 32KB: wmap alias early; ssup in resolve
    __shared__ int      plist[128];
    __shared__ float    wlist[128];
    __shared__ int      swcnt[8];
    __shared__ int      s_last;
    __shared__ unsigned sany[16];
    __shared__ unsigned sword[16];

    int k    = blockIdx.x;
    int q    = blockIdx.y;
    int tid  = threadIdx.x;
    int lane = tid & 31, wid = tid >> 5;
    float* wmap = (float*)sbig;

    if (q == 0) {
        const float4* gs = (const float4*)g_shifted;
        #pragma unroll
        for (int i = tid; i < KSEL; i += 256) sb[i] = gs[i];
    }
    for (int i = tid; i < 1024; i += 256) wmap[i] = 0.0f;
    __syncthreads();

    // weight map samples for roi k
    if (tid < NSAMP) {
        const float sc = 32.0f / 1024.0f;
        float ry1 = g_rois[k*4+0] * sc, rx1 = g_rois[k*4+1] * sc;
        float ry2 = g_rois[k*4+2] * sc, rx2 = g_rois[k*4+3] * sc;
        int sy = tid / SS_, sx = tid % SS_;
        float fy = ((float)sy + 0.5f) / (float)SS_;
        float fx = ((float)sx + 0.5f) / (float)SS_;
        float yy = ry1 + fy * (ry2 - ry1) - 0.5f;
        float xx = rx1 + fx * (rx2 - rx1) - 0.5f;
        float yc = fminf(fmaxf(yy, 0.0f), 31.0f);
        float xc = fminf(fmaxf(xx, 0.0f), 31.0f);
        float y0 = floorf(yc), x0 = floorf(xc);
        float wy = yc - y0,  wx = xc - x0;
        int y0i = (int)y0, x0i = (int)x0;
        int y1i = min(y0i + 1, 31), x1i = min(x0i + 1, 31);
        atomicAdd(&wmap[y0i*32 + x0i], (1.0f - wy) * (1.0f - wx));
        atomicAdd(&wmap[y0i*32 + x1i], (1.0f - wy) * wx);
        atomicAdd(&wmap[y1i*32 + x0i], wy * (1.0f - wx));
        atomicAdd(&wmap[y1i*32 + x1i], wy * wx);
    }
    // sup words for roi k (q==0, warp 7)
    if (q == 0 && tid >= 224 && tid < 240) {
        int t = tid - 224;
        float4 bi = sb[k];
        float ai = (bi.z - bi.x) * (bi.w - bi.y);
        unsigned bits = 0u;
        #pragma unroll 8
        for (int b = 0; b < 32; b++) {
            int j = t*32 + b;
            if (j > k) {
                float4 bj = sb[j];
                float yA = fmaxf(bi.x, bj.x), xA = fmaxf(bi.y, bj.y);
                float yB = fminf(bi.z, bj.z), xB = fminf(bi.w, bj.w);
                float inter = fmaxf(yB - yA, 0.0f) * fmaxf(xB - xA, 0.0f);
                float aj = (bj.z - bj.x) * (bj.w - bj.y);
                if (inter > NMS_IOUC * (ai + aj - inter + 1e-8f)) bits |= (1u << b);
            }
        }
        g_sup[k*16 + t] = bits;
        if (bits) atomicOr(&g_supany[k >> 5], 1u << (k & 31));
    }
    __syncthreads();

    // deterministic compaction: order = pixel index ascending (identical in
    // all 4 quarter-blocks of this roi; nonzero pattern is deterministic)
    int base = 0;
    #pragma unroll
    for (int it = 0; it < 4; it++) {
        int p = it*256 + tid;
        float w = wmap[p];
        bool nz = (w != 0.0f);
        unsigned m = __ballot_sync(0xffffffffu, nz);
        if (lane == 0) swcnt[wid] = __popc(m);
        __syncthreads();
        int wo = 0, tot = 0;
        #pragma unroll
        for (int j = 0; j < 8; j++) {
            int cj = swcnt[j];
            if (j < wid) wo += cj;
            tot += cj;
        }
        if (nz) {
            int pos = base + wo + __popc(m & ((1u << lane) - 1u));
            plist[pos] = p; wlist[pos] = w;
        }
        base += tot;
        __syncthreads();
    }
    int n = base;

    // gather quarter q of pixels, all 1024 channels (float4 per thread)
    int e0 = (n * q) >> 2;
    int e1 = (n * (q + 1)) >> 2;
    const float4* fb = (const float4*)(feats + (size_t)g_assign[k] * (HF_*WF_*CCH)) + tid;
    float ax = 0.f, ay = 0.f, az = 0.f, aw = 0.f;
    #pragma unroll 4
    for (int e = e0; e < e1; e++) {
        int   p = plist[e];
        float w = wlist[e];
        float4 vv = fb[(size_t)p * 256];
        ax += w * vv.x; ay += w * vv.y; az += w * vv.z; aw += w * vv.w;
    }
    const float inv = 1.0f / 196.0f;
    float* po = g_poolT + (size_t)q * (KSEL*CCH) + (size_t)(k >> 4) * (CCH*GRP) + (k & 15);
    int c0 = tid * 4;
    po[(size_t)(c0+0)*GRP] = ax * inv;
    po[(size_t)(c0+1)*GRP] = ay * inv;
    po[(size_t)(c0+2)*GRP] = az * inv;
    po[(size_t)(c0+3)*GRP] = aw * inv;

    // ---- grid arrival: last of 2048 blocks resolves greedy NMS ----
    __threadfence();
    __syncthreads();
    if (tid == 0) s_last = (atomicAdd(&g_done, 1) == KSEL*NQ - 1) ? 1 : 0;
    __syncthreads();
    if (!s_last) return;
    __threadfence();

    #pragma unroll
    for (int i = tid; i < KSEL*16; i += 256) sbig[i] = g_sup[i];
    #pragma unroll
    for (int q2 = 0; q2 < 2; q2++) {
        int i = q2*256 + tid;
        int v = g_valid[i];
        unsigned bm = __ballot_sync(0xffffffffu, v != 0);
        if ((i & 31) == 0) sword[i >> 5] = bm;
    }
    if (tid < 16) { sany[tid] = g_supany[tid]; g_supany[tid] = 0u; }
    if (tid == 0) g_done = 0;
    __syncthreads();

    if (tid < 32) {
        unsigned word = (tid < 16) ? sword[tid] : 0u;
        for (int ww = 0; ww < 16; ww++) {
            unsigned anyw = sany[ww];
            if (!anyw) continue;
            for (int b = 0; b < 32; b++) {
                if (!((anyw >> b) & 1u)) continue;
                int ii = ww*32 + b;
                unsigned wi = __shfl_sync(0xffffffffu, word, ww);
                if ((wi >> b) & 1u) {
                    if (tid < 16) word &= ~sbig[ii*16 + tid];
                }
            }
        }
        if (tid < 16) sword[tid] = word;
    }
    __syncthreads();
    #pragma unroll
    for (int q2 = 0; q2 < 2; q2++) {
        int i = q2*256 + tid;
        g_keep[i] = (int)((sword[i >> 5] >> (i & 31)) & 1u);
    }
}

// ====== GEMM1a: (32 groups, 16 K-chunks of 64) x 256 thr, MLP-8 prefetch ====
__global__ void __launch_bounds__(256) k_gemm1a(const float* __restrict__ W1) {
    __shared__ __align__(16) float sp[64*GRP];   // [c in chunk][16 rois] 4KB
    int g   = blockIdx.x;
    int kc  = blockIdx.y;
    int tid = threadIdx.x;   // output col

    {
        size_t off = (size_t)g * (CCH*GRP) + (size_t)kc * (64*GRP);
        const float4* s0 = (const float4*)(g_poolT + off);
        const float4* s1 = (const float4*)(g_poolT + (size_t)KSEL*CCH   + off);
        const float4* s2 = (const float4*)(g_poolT + (size_t)2*KSEL*CCH + off);
        const float4* s3 = (const float4*)(g_poolT + (size_t)3*KSEL*CCH + off);
        float4* dst = (float4*)sp;
        int i = tid;   // 64*16/4 = 256 float4 = one per thread
        float4 a = s0[i], b = s1[i], c = s2[i], d = s3[i];
        dst[i] = make_float4(a.x+b.x+c.x+d.x, a.y+b.y+c.y+d.y,
                             a.z+b.z+c.z+d.z, a.w+b.w+c.w+d.w);
    }
    __syncthreads();

    const float* w1 = W1 + (size_t)(kc * 64) * 256 + tid;
    ull a[8];
    #pragma unroll
    for (int j = 0; j < 8; j++) a[j] = 0ull;
    const ull* spu = (const ull*)sp;

    for (int c0 = 0; c0 < 64; c0 += 8) {
        float w[8];
        #pragma unroll
        for (int j = 0; j < 8; j++) w[j] = w1[(size_t)(c0 + j) * 256];  // 8 LDGs in flight
        #pragma unroll
        for (int j = 0; j < 8; j++) {
            ull w2;
            asm("mov.b64 %0, {%1, %1};" : "=l"(w2) : "r"(__float_as_uint(w[j])));
            #pragma unroll
            for (int jj = 0; jj < 8; jj++)
                asm("fma.rn.f32x2 %0, %1, %2, %0;" : "+l"(a[jj]) : "l"(spu[(c0+j)*8 + jj]), "l"(w2));
        }
    }

    float* pp = g_part + (size_t)kc * (KSEL*FEAT) + (size_t)(g * GRP) * 256 + tid;
    #pragma unroll
    for (int j = 0; j < 8; j++) {
        unsigned lo, hi;
        asm("mov.b64 {%0, %1}, %2;" : "=r"(lo), "=r"(hi) : "l"(a[j]));
        pp[(size_t)(2*j  ) * 256] = __uint_as_float(lo);
        pp[(size_t)(2*j+1) * 256] = __uint_as_float(hi);
    }
}

// ====== tail: reduce 16 partials + BN/ReLU + GEMM2 + masked out, 2 rois/blk =
__global__ void __launch_bounds__(128) k_tail(const float* __restrict__ b1,
                                              const float* __restrict__ gamma,
                                              const float* __restrict__ beta,
                                              const float* __restrict__ mm,
                                              const float* __restrict__ mv,
                                              const float* __restrict__ W2,
                                              const float* __restrict__ b2,
                                              float* __restrict__ out) {
    __shared__ float sh[2*FEAT];
    __shared__ float srois[8];
    int r0  = blockIdx.x * 2;
    int tid = threadIdx.x;
    if (tid < 8) srois[tid] = g_rois[r0*4 + tid];

    #pragma unroll
    for (int q = 0; q < 4; q++) {
        int i = q*128 + tid;          // i < 512: roi = i>>8, col = i&255
        int roi = i >> 8, col = i & 255;
        const float* pp = g_part + (size_t)(r0 + roi) * 256 + col;
        float s = 0.0f;
        #pragma unroll
        for (int kc = 0; kc < NKC; kc++) s += pp[(size_t)kc * (KSEL*FEAT)];
        float hv = (s + b1[col] - mm[col]) * rsqrtf(mv[col] + 1e-3f) * gamma[col] + beta[col];
        sh[i] = fmaxf(hv, 0.0f);
    }
    __syncthreads();

    #pragma unroll
    for (int q = 0; q < 2; q++) {
        int j = q*128 + tid;
        if (j < 168) {
            int r = (j >= 84) ? 1 : 0;
            int o = j - r*84;
            int kg = r0 + r;
            float acc = b2[o];
            const float* hrow = &sh[r*FEAT];
            #pragma unroll 4
            for (int c = 0; c < 256; c++) acc += hrow[c] * W2[c*OUTC + o];
            float keepf = (float)g_keep[kg];
            if (o < 4) out[KSEL*80 + kg*4 + o] = (srois[r*4 + o] + acc) * keepf;
            else       out[(size_t)kg*80 + (o - 4)] = acc * keepf;
        } else if (j < 170) {
            int kg = r0 + (j - 168);
            out[KSEL*80 + KSEL*4 + kg] = (float)g_keep[kg];
        }
    }
}

// ---------------- launch ----------------------------------------------------
extern "C" void kernel_launch(void* const* d_in, const int* in_sizes, int n_in,
                              void* d_out, int out_size) {
    const float* pred    = (const float*)d_in[0];
    const float* rois    = (const float*)d_in[1];
    const float* anchors = (const float*)d_in[2];
    const int*   assign  = (const int*)  d_in[3];
    const float* feats   = (const float*)d_in[4];
    const float* W1      = (const float*)d_in[5];
    const float* b1      = (const float*)d_in[6];
    const float* gamma   = (const float*)d_in[7];
    const float* beta    = (const float*)d_in[8];
    const float* mm      = (const float*)d_in[9];
    const float* mv      = (const float*)d_in[10];
    const float* W2      = (const float*)d_in[11];
    const float* b2      = (const float*)d_in[12];
    float* out = (float*)d_out;

    k_filtersel<<<NTOT/1024, 1024>>>(pred, rois, anchors, assign);
    k_gatherall<<<dim3(KSEL, NQ), 256>>>(feats);
    k_gemm1a<<<dim3(NGRP, NKC), 256>>>(W1);
    k_tail<<<KSEL / 2, 128>>>(b1, gamma, beta, mm, mv, W2, b2, out);
}

// round 12
// speedup vs baseline: 1.0851x; 1.0851x over previous
#include <cuda_runtime.h>
#include <stdint.h>

#define NTOT  (8*32*32*9)   // 73728
#define KSEL  512
#define HF_   32
#define WF_   32
#define CCH   1024
#define FEAT  256
#define OUTC  84
#define SS_   14
#define NSAMP 196
#define DET_THRC 0.7f
#define NMS_IOUC 0.7f
#define NBINS 4096
#define NKC   16                // K chunks in gemm1 (64 c each)
#define GRP   16                // rois per gemm1 group
#define NGRP  (KSEL/GRP)        // 32
#define NQ    4                 // pixel quarters in gather

typedef unsigned long long ull;

// ---------------- device scratch (static globals; zero-initialized) ---------
__device__ uint64_t g_cand[NTOT];
__device__ int      g_cand_count;                 // reset by select phase
__device__ __align__(16) int g_hist[NBINS];       // reset by select phase
__device__ int      g_fdone;                      // reset by select phase
__device__ int      g_valid[KSEL];
__device__ int      g_assign[KSEL];
__device__ float    g_rois[KSEL*4];
__device__ float    g_shifted[KSEL*4];
__device__ unsigned g_sup[KSEL*16];
__device__ unsigned g_supany[16];                 // reset by resolver
__device__ int      g_keep[KSEL];
__device__ int      g_done;                       // reset by resolver
__device__ __align__(16) float g_poolT[NQ*KSEL*CCH];    // [q][grp][c][k%16]
__device__ __align__(16) float g_part[NKC*KSEL*FEAT];   // [kc][roi][col]

// ====== fused filter (72 x 1024) + last-block top-K select ==================
__global__ void __launch_bounds__(1024) k_filtersel(const float* __restrict__ pred,
                                                    const float* __restrict__ rois,
                                                    const float* __restrict__ anchors,
                                                    const int*   __restrict__ assign) {
    __shared__ int s_last;
    int tid = threadIdx.x;
    {
        int i = blockIdx.x * 1024 + tid;
        float s = pred[i];
        bool c = (s > DET_THRC);
        unsigned m = __ballot_sync(0xffffffffu, c);
        int n = __popc(m);
        int base = 0;
        if ((tid & 31) == 0 && n)
            base = atomicAdd(&g_cand_count, n);
        base = __shfl_sync(0xffffffffu, base, 0);
        if (c) {
            int r = __popc(m & ((1u << (tid & 31)) - 1u));
            unsigned u = __float_as_uint(s); // s > 0 -> monotone as unsigned
            g_cand[base + r] = ((uint64_t)u << 32) | (unsigned)(0xFFFFFFFFu - (unsigned)i);
            atomicAdd(&g_hist[u >> 19], 1);
        }
    }
    __threadfence();
    __syncthreads();
    if (tid == 0) s_last = (atomicAdd(&g_fdone, 1) == 71) ? 1 : 0;
    __syncthreads();
    if (!s_last) return;
    __threadfence();

    // ---------------- select phase (single block, 1024 threads) -------------
    __shared__ int      sh_hist[NBINS];
    __shared__ int      sh_chunk[1024];
    __shared__ int      sh_warp[32];
    __shared__ unsigned sh_T;
    __shared__ int      sh_cnt;
    __shared__ uint64_t sh_keys[1024];
    int lane = tid & 31, wid = tid >> 5;

    int M = g_cand_count; if (M > NTOT) M = NTOT;
    __syncthreads();
    if (tid == 0) { g_cand_count = 0; sh_cnt = 0; g_fdone = 0; }

    int4 h = ((const int4*)g_hist)[tid];
    ((int4*)g_hist)[tid] = make_int4(0, 0, 0, 0);
    sh_hist[tid*4+0] = h.x; sh_hist[tid*4+1] = h.y;
    sh_hist[tid*4+2] = h.z; sh_hist[tid*4+3] = h.w;
    int csum = h.x + h.y + h.z + h.w;
    sh_chunk[tid] = csum;
    int ws = csum;
    #pragma unroll
    for (int off = 16; off > 0; off >>= 1) ws += __shfl_down_sync(0xffffffffu, ws, off);
    if (lane == 0) sh_warp[wid] = ws;
    __syncthreads();

    if (tid == 0) {
        unsigned T = 1u;
        int cum = 0; int w;
        bool found = false;
        for (w = 31; w >= 0; w--) {
            if (cum + sh_warp[w] >= KSEL) { found = true; break; }
            cum += sh_warp[w];
        }
        if (found) {
            int c;
            for (c = 31; c >= 0; c--) {
                int t = sh_chunk[w*32 + c];
                if (cum + t >= KSEL) break;
                cum += t;
            }
            int base = (w*32 + c) * 4;
            int b;
            for (b = 3; b >= 0; b--) {
                int t = sh_hist[base + b];
                if (cum + t >= KSEL) break;
                cum += t;
            }
            T = (unsigned)(base + b) << 19;
        }
        sh_T = T;
    }
    __syncthreads();
    unsigned T = sh_T;

    for (int j = tid; j < M; j += 1024) {
        uint64_t k = g_cand[j];
        if ((unsigned)(k >> 32) >= T) {
            int p = atomicAdd(&sh_cnt, 1);
            if (p < 1024) sh_keys[p] = k;
        }
    }
    __syncthreads();
    int cnt = sh_cnt; if (cnt > 1024) cnt = 1024;
    if (tid >= cnt) sh_keys[tid] = 0ull;
    __syncthreads();

    // hybrid bitonic sort (descending)
    uint64_t v = sh_keys[tid];
    #pragma unroll
    for (int size = 2; size <= 32; size <<= 1) {
        #pragma unroll
        for (int stride = size >> 1; stride >= 1; stride >>= 1) {
            uint64_t o = __shfl_xor_sync(0xffffffffu, v, stride);
            bool lower = (tid & stride) == 0;
            bool desc  = (tid & size) == 0;
            uint64_t mx = v > o ? v : o, mn = v > o ? o : v;
            v = (desc == lower) ? mx : mn;
        }
    }
    sh_keys[tid] = v;
    __syncthreads();
    for (int size = 64; size <= 1024; size <<= 1) {
        for (int stride = size >> 1; stride >= 32; stride >>= 1) {
            int j = tid ^ stride;
            if (j > tid) {
                uint64_t a = sh_keys[tid], b = sh_keys[j];
                bool desc = (tid & size) == 0;
                if (desc ? (a < b) : (a > b)) { sh_keys[tid] = b; sh_keys[j] = a; }
            }
            __syncthreads();
        }
        v = sh_keys[tid];
        #pragma unroll
        for (int stride = 16; stride >= 1; stride >>= 1) {
            uint64_t o = __shfl_xor_sync(0xffffffffu, v, stride);
            bool lower = (tid & stride) == 0;
            bool desc  = (tid & size) == 0;
            uint64_t mx = v > o ? v : o, mn = v > o ? o : v;
            v = (desc == lower) ? mx : mn;
        }
        sh_keys[tid] = v;
        __syncthreads();
    }

    if (tid < KSEL) {
        uint64_t k = sh_keys[tid];
        unsigned u = (unsigned)(k >> 32);
        int idx = 0, vv = 0;
        if (u != 0u) { idx = (int)(0xFFFFFFFFu - (unsigned)(k & 0xFFFFFFFFu)); vv = 1; }
        g_valid[tid] = vv;
        int a = assign[idx];
        g_assign[tid] = a;
        float fa = (float)a * 1024.0f;
        #pragma unroll
        for (int c = 0; c < 4; c++) g_rois[tid*4 + c] = rois[idx*4 + c];
        float cy = anchors[idx*4+0], cx = anchors[idx*4+1];
        float hh = anchors[idx*4+2], ww = anchors[idx*4+3];
        g_shifted[tid*4+0] = cy - hh*0.5f + fa;
        g_shifted[tid*4+1] = cx - ww*0.5f + fa;
        g_shifted[tid*4+2] = cy + hh*0.5f + fa;
        g_shifted[tid*4+3] = cx + ww*0.5f + fa;
    }
}

// === gatherall: (512 rois x 4 px-quarters) x 256 thr ========================
__global__ void __launch_bounds__(256) k_gatherall(const float* __restrict__ feats) {
    __shared__ float4   sb[KSEL];          // 8KB boxes (q==0 sup + resolve reuse)
    __shared__ unsigned sbig[KSEL*16];     // 32KB: wmap alias early; ssup in resolve
    __shared__ int      plist[128];
    __shared__ float    wlist[128];
    __shared__ int      swcnt[8];
    __shared__ int      s_last;
    __shared__ unsigned sany[16];
    __shared__ unsigned sword[16];

    int k    = blockIdx.x;
    int q    = blockIdx.y;
    int tid  = threadIdx.x;
    int lane = tid & 31, wid = tid >> 5;
    float* wmap = (float*)sbig;

    if (q == 0) {
        const float4* gs = (const float4*)g_shifted;
        #pragma unroll
        for (int i = tid; i < KSEL; i += 256) sb[i] = gs[i];
    }
    for (int i = tid; i < 1024; i += 256) wmap[i] = 0.0f;
    __syncthreads();

    // weight map samples for roi k
    if (tid < NSAMP) {
        const float sc = 32.0f / 1024.0f;
        float ry1 = g_rois[k*4+0] * sc, rx1 = g_rois[k*4+1] * sc;
        float ry2 = g_rois[k*4+2] * sc, rx2 = g_rois[k*4+3] * sc;
        int sy = tid / SS_, sx = tid % SS_;
        float fy = ((float)sy + 0.5f) / (float)SS_;
        float fx = ((float)sx + 0.5f) / (float)SS_;
        float yy = ry1 + fy * (ry2 - ry1) - 0.5f;
        float xx = rx1 + fx * (rx2 - rx1) - 0.5f;
        float yc = fminf(fmaxf(yy, 0.0f), 31.0f);
        float xc = fminf(fmaxf(xx, 0.0f), 31.0f);
        float y0 = floorf(yc), x0 = floorf(xc);
        float wy = yc - y0,  wx = xc - x0;
        int y0i = (int)y0, x0i = (int)x0;
        int y1i = min(y0i + 1, 31), x1i = min(x0i + 1, 31);
        atomicAdd(&wmap[y0i*32 + x0i], (1.0f - wy) * (1.0f - wx));
        atomicAdd(&wmap[y0i*32 + x1i], (1.0f - wy) * wx);
        atomicAdd(&wmap[y1i*32 + x0i], wy * (1.0f - wx));
        atomicAdd(&wmap[y1i*32 + x1i], wy * wx);
    }
    // sup words for roi k (q==0, warp 7)
    if (q == 0 && tid >= 224 && tid < 240) {
        int t = tid - 224;
        float4 bi = sb[k];
        float ai = (bi.z - bi.x) * (bi.w - bi.y);
        unsigned bits = 0u;
        #pragma unroll 8
        for (int b = 0; b < 32; b++) {
            int j = t*32 + b;
            if (j > k) {
                float4 bj = sb[j];
                float yA = fmaxf(bi.x, bj.x), xA = fmaxf(bi.y, bj.y);
                float yB = fminf(bi.z, bj.z), xB = fminf(bi.w, bj.w);
                float inter = fmaxf(yB - yA, 0.0f) * fmaxf(xB - xA, 0.0f);
                float aj = (bj.z - bj.x) * (bj.w - bj.y);
                if (inter > NMS_IOUC * (ai + aj - inter + 1e-8f)) bits |= (1u << b);
            }
        }
        g_sup[k*16 + t] = bits;
        if (bits) atomicOr(&g_supany[k >> 5], 1u << (k & 31));
    }
    __syncthreads();

    // deterministic compaction: order = pixel index ascending (identical in
    // all 4 quarter-blocks of this roi)
    int base = 0;
    #pragma unroll
    for (int it = 0; it < 4; it++) {
        int p = it*256 + tid;
        float w = wmap[p];
        bool nz = (w != 0.0f);
        unsigned m = __ballot_sync(0xffffffffu, nz);
        if (lane == 0) swcnt[wid] = __popc(m);
        __syncthreads();
        int wo = 0, tot = 0;
        #pragma unroll
        for (int j = 0; j < 8; j++) {
            int cj = swcnt[j];
            if (j < wid) wo += cj;
            tot += cj;
        }
        if (nz) {
            int pos = base + wo + __popc(m & ((1u << lane) - 1u));
            plist[pos] = p; wlist[pos] = w;
        }
        base += tot;
        __syncthreads();
    }
    int n = base;

    // gather quarter q of pixels, all 1024 channels (float4 per thread)
    int e0 = (n * q) >> 2;
    int e1 = (n * (q + 1)) >> 2;
    const float4* fb = (const float4*)(feats + (size_t)g_assign[k] * (HF_*WF_*CCH)) + tid;
    float ax = 0.f, ay = 0.f, az = 0.f, aw = 0.f;
    #pragma unroll 4
    for (int e = e0; e < e1; e++) {
        int   p = plist[e];
        float w = wlist[e];
        float4 vv = fb[(size_t)p * 256];
        ax += w * vv.x; ay += w * vv.y; az += w * vv.z; aw += w * vv.w;
    }
    const float inv = 1.0f / 196.0f;
    float* po = g_poolT + (size_t)q * (KSEL*CCH) + (size_t)(k >> 4) * (CCH*GRP) + (k & 15);
    int c0 = tid * 4;
    po[(size_t)(c0+0)*GRP] = ax * inv;
    po[(size_t)(c0+1)*GRP] = ay * inv;
    po[(size_t)(c0+2)*GRP] = az * inv;
    po[(size_t)(c0+3)*GRP] = aw * inv;

    // ---- grid arrival: last of 2048 blocks resolves greedy NMS ----
    __threadfence();
    __syncthreads();
    if (tid == 0) s_last = (atomicAdd(&g_done, 1) == KSEL*NQ - 1) ? 1 : 0;
    __syncthreads();
    if (!s_last) return;
    __threadfence();

    #pragma unroll
    for (int i = tid; i < KSEL*16; i += 256) sbig[i] = g_sup[i];
    #pragma unroll
    for (int q2 = 0; q2 < 2; q2++) {
        int i = q2*256 + tid;
        int v = g_valid[i];
        unsigned bm = __ballot_sync(0xffffffffu, v != 0);
        if ((i & 31) == 0) sword[i >> 5] = bm;
    }
    if (tid < 16) { sany[tid] = g_supany[tid]; g_supany[tid] = 0u; }
    if (tid == 0) g_done = 0;
    __syncthreads();

    if (tid < 32) {
        unsigned word = (tid < 16) ? sword[tid] : 0u;
        for (int ww = 0; ww < 16; ww++) {
            unsigned anyw = sany[ww];
            if (!anyw) continue;
            for (int b = 0; b < 32; b++) {
                if (!((anyw >> b) & 1u)) continue;
                int ii = ww*32 + b;
                unsigned wi = __shfl_sync(0xffffffffu, word, ww);
                if ((wi >> b) & 1u) {
                    if (tid < 16) word &= ~sbig[ii*16 + tid];
                }
            }
        }
        if (tid < 16) sword[tid] = word;
    }
    __syncthreads();
    #pragma unroll
    for (int q2 = 0; q2 < 2; q2++) {
        int i = q2*256 + tid;
        g_keep[i] = (int)((sword[i >> 5] >> (i & 31)) & 1u);
    }
}

// ====== GEMM1a: (32 groups, 16 K-chunks of 64) x 256 thr, MLP-8 prefetch ====
__global__ void __launch_bounds__(256) k_gemm1a(const float* __restrict__ W1) {
    __shared__ __align__(16) float sp[64*GRP];   // [c in chunk][16 rois] 4KB
    int g   = blockIdx.x;
    int kc  = blockIdx.y;
    int tid = threadIdx.x;   // output col

    {
        size_t off = (size_t)g * (CCH*GRP) + (size_t)kc * (64*GRP);
        const float4* s0 = (const float4*)(g_poolT + off);
        const float4* s1 = (const float4*)(g_poolT + (size_t)KSEL*CCH   + off);
        const float4* s2 = (const float4*)(g_poolT + (size_t)2*KSEL*CCH + off);
        const float4* s3 = (const float4*)(g_poolT + (size_t)3*KSEL*CCH + off);
        float4* dst = (float4*)sp;
        int i = tid;   // 64*16/4 = 256 float4 = one per thread
        float4 a = s0[i], b = s1[i], c = s2[i], d = s3[i];
        dst[i] = make_float4(a.x+b.x+c.x+d.x, a.y+b.y+c.y+d.y,
                             a.z+b.z+c.z+d.z, a.w+b.w+c.w+d.w);
    }
    __syncthreads();

    const float* w1 = W1 + (size_t)(kc * 64) * 256 + tid;
    ull a[8];
    #pragma unroll
    for (int j = 0; j < 8; j++) a[j] = 0ull;
    const ull* spu = (const ull*)sp;

    for (int c0 = 0; c0 < 64; c0 += 8) {
        float w[8];
        #pragma unroll
        for (int j = 0; j < 8; j++) w[j] = w1[(size_t)(c0 + j) * 256];  // 8 LDGs in flight
        #pragma unroll
        for (int j = 0; j < 8; j++) {
            ull w2;
            asm("mov.b64 %0, {%1, %1};" : "=l"(w2) : "r"(__float_as_uint(w[j])));
            #pragma unroll
            for (int jj = 0; jj < 8; jj++)
                asm("fma.rn.f32x2 %0, %1, %2, %0;" : "+l"(a[jj]) : "l"(spu[(c0+j)*8 + jj]), "l"(w2));
        }
    }

    float* pp = g_part + (size_t)kc * (KSEL*FEAT) + (size_t)(g * GRP) * 256 + tid;
    #pragma unroll
    for (int j = 0; j < 8; j++) {
        unsigned lo, hi;
        asm("mov.b64 {%0, %1}, %2;" : "=r"(lo), "=r"(hi) : "l"(a[j]));
        pp[(size_t)(2*j  ) * 256] = __uint_as_float(lo);
        pp[(size_t)(2*j+1) * 256] = __uint_as_float(hi);
    }
}

// ====== tail v2: 1 roi/block, 512 blocks x 256 thr ==========================
// phase1: thread=col reduces 16 partials + BN/ReLU -> sh[256]
// phase2: thread=(out, c-half) 168 threads x 128-dot (unroll 8), combine halves
__global__ void __launch_bounds__(256) k_tail(const float* __restrict__ b1,
                                              const float* __restrict__ gamma,
                                              const float* __restrict__ beta,
                                              const float* __restrict__ mm,
                                              const float* __restrict__ mv,
                                              const float* __restrict__ W2,
                                              const float* __restrict__ b2,
                                              float* __restrict__ out) {
    __shared__ float sh[FEAT];
    __shared__ float shalf[2][OUTC];
    int k   = blockIdx.x;
    int tid = threadIdx.x;

    {
        const float* pp = g_part + (size_t)k * 256 + tid;
        float s = 0.0f;
        #pragma unroll
        for (int kc = 0; kc < NKC; kc++) s += pp[(size_t)kc * (KSEL*FEAT)];
        float hv = (s + b1[tid] - mm[tid]) * rsqrtf(mv[tid] + 1e-3f) * gamma[tid] + beta[tid];
        sh[tid] = fmaxf(hv, 0.0f);
    }
    __syncthreads();

    if (tid < 2*OUTC) {
        int o  = tid >> 1;
        int hf = tid & 1;
        const float* w2   = W2 + (size_t)(hf * 128) * OUTC + o;
        const float* hrow = sh + hf * 128;
        float acc = 0.0f;
        #pragma unroll 8
        for (int c = 0; c < 128; c++) acc += hrow[c] * w2[(size_t)c * OUTC];
        shalf[hf][o] = acc;
    }
    __syncthreads();

    if (tid < OUTC) {
        float acc = b2[tid] + shalf[0][tid] + shalf[1][tid];
        float keepf = (float)g_keep[k];
        if (tid < 4) out[KSEL*80 + k*4 + tid] = (g_rois[k*4 + tid] + acc) * keepf;
        else         out[(size_t)k*80 + (tid - 4)] = acc * keepf;
    }
    if (tid == 255) out[KSEL*80 + KSEL*4 + k] = (float)g_keep[k];
}

// ---------------- launch ----------------------------------------------------
extern "C" void kernel_launch(void* const* d_in, const int* in_sizes, int n_in,
                              void* d_out, int out_size) {
    const float* pred    = (const float*)d_in[0];
    const float* rois    = (const float*)d_in[1];
    const float* anchors = (const float*)d_in[2];
    const int*   assign  = (const int*)  d_in[3];
    const float* feats   = (const float*)d_in[4];
    const float* W1      = (const float*)d_in[5];
    const float* b1      = (const float*)d_in[6];
    const float* gamma   = (const float*)d_in[7];
    const float* beta    = (const float*)d_in[8];
    const float* mm      = (const float*)d_in[9];
    const float* mv      = (const float*)d_in[10];
    const float* W2      = (const float*)d_in[11];
    const float* b2      = (const float*)d_in[12];
    float* out = (float*)d_out;

    k_filtersel<<<NTOT/1024, 1024>>>(pred, rois, anchors, assign);
    k_gatherall<<<dim3(KSEL, NQ), 256>>>(feats);
    k_gemm1a<<<dim3(NGRP, NKC), 256>>>(W1);
    k_tail<<<KSEL, 256>>>(b1, gamma, beta, mm, mv, W2, b2, out);
}

// round 14
// speedup vs baseline: 1.1074x; 1.0205x over previous
#include <cuda_runtime.h>
#include <stdint.h>

#define NTOT  (8*32*32*9)   // 73728
#define KSEL  512
#define HF_   32
#define WF_   32
#define CCH   1024
#define FEAT  256
#define OUTC  84
#define SS_   14
#define NSAMP 196
#define DET_THRC 0.7f
#define NMS_IOUC 0.7f
#define NBINS 4096
#define NKC   16                // K chunks in gemm1 (64 c each)
#define GRP   16                // rois per gemm1 group
#define NGRP  (KSEL/GRP)        // 32
#define NQ    4                 // pixel quarters in gather

typedef unsigned long long ull;

// ---------------- device scratch (static globals; zero-initialized) ---------
__device__ uint64_t g_cand[NTOT];
__device__ int      g_cand_count;                 // reset by select phase
__device__ __align__(16) int g_hist[NBINS];       // reset by select phase
__device__ int      g_fdone;                      // reset by select phase
__device__ int      g_valid[KSEL];
__device__ int      g_assign[KSEL];
__device__ float    g_rois[KSEL*4];
__device__ float    g_shifted[KSEL*4];
__device__ unsigned g_sup[KSEL*16];
__device__ unsigned g_supany[16];                 // reset by resolver
__device__ int      g_keep[KSEL];
__device__ int      g_done;                       // reset by resolver
__device__ __align__(16) float g_W2T[OUTC*FEAT];  // W2 transposed [o][c]
__device__ __align__(16) float g_poolT[NQ*KSEL*CCH];    // [q][grp][c][k%16]
__device__ __align__(16) float g_part[NKC*KSEL*FEAT];   // [kc][roi][col]

// ====== fused filter (72 x 1024) + W2 transpose + last-block top-K select ===
__global__ void __launch_bounds__(1024) k_filtersel(const float* __restrict__ pred,
                                                    const float* __restrict__ rois,
                                                    const float* __restrict__ anchors,
                                                    const int*   __restrict__ assign,
                                                    const float* __restrict__ W2) {
    __shared__ int s_last;
    int tid = threadIdx.x;
    {
        int i = blockIdx.x * 1024 + tid;
        float s = pred[i];
        bool c = (s > DET_THRC);
        unsigned m = __ballot_sync(0xffffffffu, c);
        int n = __popc(m);
        int base = 0;
        if ((tid & 31) == 0 && n)
            base = atomicAdd(&g_cand_count, n);
        base = __shfl_sync(0xffffffffu, base, 0);
        if (c) {
            int r = __popc(m & ((1u << (tid & 31)) - 1u));
            unsigned u = __float_as_uint(s); // s > 0 -> monotone as unsigned
            g_cand[base + r] = ((uint64_t)u << 32) | (unsigned)(0xFFFFFFFFu - (unsigned)i);
            atomicAdd(&g_hist[u >> 19], 1);
        }
        // W2 transpose for the tail (each element written exactly once)
        if (i < OUTC * FEAT) {
            int o = i >> 8;
            int cc = i & 255;
            g_W2T[o * 256 + cc] = W2[cc * OUTC + o];
        }
    }
    __threadfence();
    __syncthreads();
    if (tid == 0) s_last = (atomicAdd(&g_fdone, 1) == 71) ? 1 : 0;
    __syncthreads();
    if (!s_last) return;
    __threadfence();

    // ---------------- select phase (single block, 1024 threads) -------------
    __shared__ int      sh_hist[NBINS];
    __shared__ int      sh_chunk[1024];
    __shared__ int      sh_warp[32];
    __shared__ unsigned sh_T;
    __shared__ int      sh_cnt;
    __shared__ uint64_t sh_keys[1024];
    int lane = tid & 31, wid = tid >> 5;

    int M = g_cand_count; if (M > NTOT) M = NTOT;
    __syncthreads();
    if (tid == 0) { g_cand_count = 0; sh_cnt = 0; g_fdone = 0; }

    int4 h = ((const int4*)g_hist)[tid];
    ((int4*)g_hist)[tid] = make_int4(0, 0, 0, 0);
    sh_hist[tid*4+0] = h.x; sh_hist[tid*4+1] = h.y;
    sh_hist[tid*4+2] = h.z; sh_hist[tid*4+3] = h.w;
    int csum = h.x + h.y + h.z + h.w;
    sh_chunk[tid] = csum;
    int ws = csum;
    #pragma unroll
    for (int off = 16; off > 0; off >>= 1) ws += __shfl_down_sync(0xffffffffu, ws, off);
    if (lane == 0) sh_warp[wid] = ws;
    __syncthreads();

    if (tid == 0) {
        unsigned T = 1u;
        int cum = 0; int w;
        bool found = false;
        for (w = 31; w >= 0; w--) {
            if (cum + sh_warp[w] >= KSEL) { found = true; break; }
            cum += sh_warp[w];
        }
        if (found) {
            int c;
            for (c = 31; c >= 0; c--) {
                int t = sh_chunk[w*32 + c];
                if (cum + t >= KSEL) break;
                cum += t;
            }
            int base = (w*32 + c) * 4;
            int b;
            for (b = 3; b >= 0; b--) {
                int t = sh_hist[base + b];
                if (cum + t >= KSEL) break;
                cum += t;
            }
            T = (unsigned)(base + b) << 19;
        }
        sh_T = T;
    }
    __syncthreads();
    unsigned T = sh_T;

    for (int j = tid; j < M; j += 1024) {
        uint64_t k = g_cand[j];
        if ((unsigned)(k >> 32) >= T) {
            int p = atomicAdd(&sh_cnt, 1);
            if (p < 1024) sh_keys[p] = k;
        }
    }
    __syncthreads();
    int cnt = sh_cnt; if (cnt > 1024) cnt = 1024;
    if (tid >= cnt) sh_keys[tid] = 0ull;
    __syncthreads();

    // hybrid bitonic sort (descending)
    uint64_t v = sh_keys[tid];
    #pragma unroll
    for (int size = 2; size <= 32; size <<= 1) {
        #pragma unroll
        for (int stride = size >> 1; stride >= 1; stride >>= 1) {
            uint64_t o = __shfl_xor_sync(0xffffffffu, v, stride);
            bool lower = (tid & stride) == 0;
            bool desc  = (tid & size) == 0;
            uint64_t mx = v > o ? v : o, mn = v > o ? o : v;
            v = (desc == lower) ? mx : mn;
        }
    }
    sh_keys[tid] = v;
    __syncthreads();
    for (int size = 64; size <= 1024; size <<= 1) {
        for (int stride = size >> 1; stride >= 32; stride >>= 1) {
            int j = tid ^ stride;
            if (j > tid) {
                uint64_t a = sh_keys[tid], b = sh_keys[j];
                bool desc = (tid & size) == 0;
                if (desc ? (a < b) : (a > b)) { sh_keys[tid] = b; sh_keys[j] = a; }
            }
            __syncthreads();
        }
        v = sh_keys[tid];
        #pragma unroll
        for (int stride = 16; stride >= 1; stride >>= 1) {
            uint64_t o = __shfl_xor_sync(0xffffffffu, v, stride);
            bool lower = (tid & stride) == 0;
            bool desc  = (tid & size) == 0;
            uint64_t mx = v > o ? v : o, mn = v > o ? o : v;
            v = (desc == lower) ? mx : mn;
        }
        sh_keys[tid] = v;
        __syncthreads();
    }

    if (tid < KSEL) {
        uint64_t k = sh_keys[tid];
        unsigned u = (unsigned)(k >> 32);
        int idx = 0, vv = 0;
        if (u != 0u) { idx = (int)(0xFFFFFFFFu - (unsigned)(k & 0xFFFFFFFFu)); vv = 1; }
        g_valid[tid] = vv;
        int a = assign[idx];
        g_assign[tid] = a;
        float fa = (float)a * 1024.0f;
        #pragma unroll
        for (int c = 0; c < 4; c++) g_rois[tid*4 + c] = rois[idx*4 + c];
        float cy = anchors[idx*4+0], cx = anchors[idx*4+1];
        float hh = anchors[idx*4+2], ww = anchors[idx*4+3];
        g_shifted[tid*4+0] = cy - hh*0.5f + fa;
        g_shifted[tid*4+1] = cx - ww*0.5f + fa;
        g_shifted[tid*4+2] = cy + hh*0.5f + fa;
        g_shifted[tid*4+3] = cx + ww*0.5f + fa;
    }
}

// === gatherall: (512 rois x 4 px-quarters) x 256 thr, slim smem =============
__global__ void __launch_bounds__(256) k_gatherall(const float* __restrict__ feats) {
    __shared__ float4   sb[KSEL];          // 8KB boxes (q==0 sup only)
    __shared__ float    wmap[1024];        // 4KB; resolver reuses as sup cache
    __shared__ int      plist[128];
    __shared__ float    wlist[128];
    __shared__ int      swcnt[8];
    __shared__ int      s_last;
    __shared__ unsigned sany[16];
    __shared__ unsigned sword[16];

    int k    = blockIdx.x;
    int q    = blockIdx.y;
    int tid  = threadIdx.x;
    int lane = tid & 31, wid = tid >> 5;

    if (q == 0) {
        const float4* gs = (const float4*)g_shifted;
        #pragma unroll
        for (int i = tid; i < KSEL; i += 256) sb[i] = gs[i];
    }
    for (int i = tid; i < 1024; i += 256) wmap[i] = 0.0f;
    __syncthreads();

    // weight map samples for roi k
    if (tid < NSAMP) {
        const float sc = 32.0f / 1024.0f;
        float ry1 = g_rois[k*4+0] * sc, rx1 = g_rois[k*4+1] * sc;
        float ry2 = g_rois[k*4+2] * sc, rx2 = g_rois[k*4+3] * sc;
        int sy = tid / SS_, sx = tid % SS_;
        float fy = ((float)sy + 0.5f) / (float)SS_;
        float fx = ((float)sx + 0.5f) / (float)SS_;
        float yy = ry1 + fy * (ry2 - ry1) - 0.5f;
        float xx = rx1 + fx * (rx2 - rx1) - 0.5f;
        float yc = fminf(fmaxf(yy, 0.0f), 31.0f);
        float xc = fminf(fmaxf(xx, 0.0f), 31.0f);
        float y0 = floorf(yc), x0 = floorf(xc);
        float wy = yc - y0,  wx = xc - x0;
        int y0i = (int)y0, x0i = (int)x0;
        int y1i = min(y0i + 1, 31), x1i = min(x0i + 1, 31);
        atomicAdd(&wmap[y0i*32 + x0i], (1.0f - wy) * (1.0f - wx));
        atomicAdd(&wmap[y0i*32 + x1i], (1.0f - wy) * wx);
        atomicAdd(&wmap[y1i*32 + x0i], wy * (1.0f - wx));
        atomicAdd(&wmap[y1i*32 + x1i], wy * wx);
    }
    // sup words for roi k (q==0, warp 7)
    if (q == 0 && tid >= 224 && tid < 240) {
        int t = tid - 224;
        float4 bi = sb[k];
        float ai = (bi.z - bi.x) * (bi.w - bi.y);
        unsigned bits = 0u;
        #pragma unroll 8
        for (int b = 0; b < 32; b++) {
            int j = t*32 + b;
            if (j > k) {
                float4 bj = sb[j];
                float yA = fmaxf(bi.x, bj.x), xA = fmaxf(bi.y, bj.y);
                float yB = fminf(bi.z, bj.z), xB = fminf(bi.w, bj.w);
                float inter = fmaxf(yB - yA, 0.0f) * fmaxf(xB - xA, 0.0f);
                float aj = (bj.z - bj.x) * (bj.w - bj.y);
                if (inter > NMS_IOUC * (ai + aj - inter + 1e-8f)) bits |= (1u << b);
            }
        }
        g_sup[k*16 + t] = bits;
        if (bits) atomicOr(&g_supany[k >> 5], 1u << (k & 31));
    }
    __syncthreads();

    // deterministic compaction (pixel index ascending; identical in all quarters)
    int base = 0;
    #pragma unroll
    for (int it = 0; it < 4; it++) {
        int p = it*256 + tid;
        float w = wmap[p];
        bool nz = (w != 0.0f);
        unsigned m = __ballot_sync(0xffffffffu, nz);
        if (lane == 0) swcnt[wid] = __popc(m);
        __syncthreads();
        int wo = 0, tot = 0;
        #pragma unroll
        for (int j = 0; j < 8; j++) {
            int cj = swcnt[j];
            if (j < wid) wo += cj;
            tot += cj;
        }
        if (nz) {
            int pos = base + wo + __popc(m & ((1u << lane) - 1u));
            plist[pos] = p; wlist[pos] = w;
        }
        base += tot;
        __syncthreads();
    }
    int n = base;

    // gather quarter q of pixels, all 1024 channels (float4 per thread)
    int e0 = (n * q) >> 2;
    int e1 = (n * (q + 1)) >> 2;
    const float4* fb = (const float4*)(feats + (size_t)g_assign[k] * (HF_*WF_*CCH)) + tid;
    float ax = 0.f, ay = 0.f, az = 0.f, aw = 0.f;
    #pragma unroll 4
    for (int e = e0; e < e1; e++) {
        int   p = plist[e];
        float w = wlist[e];
        float4 vv = fb[(size_t)p * 256];
        ax += w * vv.x; ay += w * vv.y; az += w * vv.z; aw += w * vv.w;
    }
    const float inv = 1.0f / 196.0f;
    float* po = g_poolT + (size_t)q * (KSEL*CCH) + (size_t)(k >> 4) * (CCH*GRP) + (k & 15);
    int c0 = tid * 4;
    po[(size_t)(c0+0)*GRP] = ax * inv;
    po[(size_t)(c0+1)*GRP] = ay * inv;
    po[(size_t)(c0+2)*GRP] = az * inv;
    po[(size_t)(c0+3)*GRP] = aw * inv;

    // ---- grid arrival: last of 2048 blocks resolves greedy NMS ----
    __threadfence();
    __syncthreads();
    if (tid == 0) s_last = (atomicAdd(&g_done, 1) == KSEL*NQ - 1) ? 1 : 0;
    __syncthreads();
    if (!s_last) return;
    __threadfence();

    if (tid < 16) { sany[tid] = g_supany[tid]; g_supany[tid] = 0u; }
    if (tid == 0) g_done = 0;
    #pragma unroll
    for (int q2 = 0; q2 < 2; q2++) {
        int i = q2*256 + tid;
        int v = g_valid[i];
        unsigned bm = __ballot_sync(0xffffffffu, v != 0);
        if ((i & 31) == 0) sword[i >> 5] = bm;
    }
    __syncthreads();

    // cache first 64 active sup rows (rank = ascending row order) in wmap space
    unsigned* cache = (unsigned*)wmap;    // 1024 words = 64 rows x 16
    #pragma unroll
    for (int q2 = 0; q2 < 2; q2++) {
        int i = q2*256 + tid;
        int w = i >> 5, b = i & 31;
        if ((sany[w] >> b) & 1u) {
            int rank = 0;
            for (int j = 0; j < w; j++) rank += __popc(sany[j]);
            rank += __popc(sany[w] & ((1u << b) - 1u));
            if (rank < 64) {
                #pragma unroll
                for (int j = 0; j < 16; j++) cache[rank*16 + j] = g_sup[i*16 + j];
            }
        }
    }
    __syncthreads();

    if (tid < 32) {
        unsigned word = (tid < 16) ? sword[tid] : 0u;
        int r = 0;
        for (int ww = 0; ww < 16; ww++) {
            unsigned anyw = sany[ww];
            if (!anyw) continue;
            for (int b = 0; b < 32; b++) {
                if (!((anyw >> b) & 1u)) continue;
                int ii = ww*32 + b;
                unsigned wi = __shfl_sync(0xffffffffu, word, ww);
                if ((wi >> b) & 1u) {
                    unsigned supw = (r < 64) ? cache[r*16 + (tid & 15)]
                                             : g_sup[ii*16 + (tid & 15)];
                    if (tid < 16) word &= ~supw;
                }
                r++;
            }
        }
        if (tid < 16) sword[tid] = word;
    }
    __syncthreads();
    #pragma unroll
    for (int q2 = 0; q2 < 2; q2++) {
        int i = q2*256 + tid;
        g_keep[i] = (int)((sword[i >> 5] >> (i & 31)) & 1u);
    }
}

// ====== GEMM1a: (32 groups, 16 K-chunks of 64) x 256 thr, MLP-8 prefetch ====
__global__ void __launch_bounds__(256) k_gemm1a(const float* __restrict__ W1) {
    __shared__ __align__(16) float sp[64*GRP];   // [c in chunk][16 rois] 4KB
    int g   = blockIdx.x;
    int kc  = blockIdx.y;
    int tid = threadIdx.x;   // output col

    {
        size_t off = (size_t)g * (CCH*GRP) + (size_t)kc * (64*GRP);
        const float4* s0 = (const float4*)(g_poolT + off);
        const float4* s1 = (const float4*)(g_poolT + (size_t)KSEL*CCH   + off);
        const float4* s2 = (const float4*)(g_poolT + (size_t)2*KSEL*CCH + off);
        const float4* s3 = (const float4*)(g_poolT + (size_t)3*KSEL*CCH + off);
        float4* dst = (float4*)sp;
        int i = tid;   // 64*16/4 = 256 float4 = one per thread
        float4 a = s0[i], b = s1[i], c = s2[i], d = s3[i];
        dst[i] = make_float4(a.x+b.x+c.x+d.x, a.y+b.y+c.y+d.y,
                             a.z+b.z+c.z+d.z, a.w+b.w+c.w+d.w);
    }
    __syncthreads();

    const float* w1 = W1 + (size_t)(kc * 64) * 256 + tid;
    ull a[8];
    #pragma unroll
    for (int j = 0; j < 8; j++) a[j] = 0ull;
    const ull* spu = (const ull*)sp;

    for (int c0 = 0; c0 < 64; c0 += 8) {
        float w[8];
        #pragma unroll
        for (int j = 0; j < 8; j++) w[j] = w1[(size_t)(c0 + j) * 256];  // 8 LDGs in flight
        #pragma unroll
        for (int j = 0; j < 8; j++) {
            ull w2;
            asm("mov.b64 %0, {%1, %1};" : "=l"(w2) : "r"(__float_as_uint(w[j])));
            #pragma unroll
            for (int jj = 0; jj < 8; jj++)
                asm("fma.rn.f32x2 %0, %1, %2, %0;" : "+l"(a[jj]) : "l"(spu[(c0+j)*8 + jj]), "l"(w2));
        }
    }

    float* pp = g_part + (size_t)kc * (KSEL*FEAT) + (size_t)(g * GRP) * 256 + tid;
    #pragma unroll
    for (int j = 0; j < 8; j++) {
        unsigned lo, hi;
        asm("mov.b64 {%0, %1}, %2;" : "=r"(lo), "=r"(hi) : "l"(a[j]));
        pp[(size_t)(2*j  ) * 256] = __uint_as_float(lo);
        pp[(size_t)(2*j+1) * 256] = __uint_as_float(hi);
    }
}

// ====== tail v3: 1 roi/block, 512 blocks x 256 thr, W2T float4 phase-2 ======
__global__ void __launch_bounds__(256) k_tail(const float* __restrict__ b1,
                                              const float* __restrict__ gamma,
                                              const float* __restrict__ beta,
                                              const float* __restrict__ mm,
                                              const float* __restrict__ mv,
                                              const float* __restrict__ b2,
                                              float* __restrict__ out) {
    __shared__ __align__(16) float sh[FEAT];
    __shared__ float shalf[2][OUTC];
    int k   = blockIdx.x;
    int tid = threadIdx.x;

    {
        const float* pp = g_part + (size_t)k * 256 + tid;
        float s = 0.0f;
        #pragma unroll
        for (int kc = 0; kc < NKC; kc++) s += pp[(size_t)kc * (KSEL*FEAT)];
        float hv = (s + b1[tid] - mm[tid]) * rsqrtf(mv[tid] + 1e-3f) * gamma[tid] + beta[tid];
        sh[tid] = fmaxf(hv, 0.0f);
    }
    __syncthreads();

    if (tid < 2*OUTC) {
        int o  = tid >> 1;
        int hf = tid & 1;
        const float4* w4 = (const float4*)g_W2T + o*64 + hf*32;
        const float4* h4 = (const float4*)sh + hf*32;
        float acc = 0.0f;
        #pragma unroll 8
        for (int c = 0; c < 32; c++) {
            float4 w = w4[c], hh = h4[c];
            acc += w.x*hh.x + w.y*hh.y + w.z*hh.z + w.w*hh.w;
        }
        shalf[hf][o] = acc;
    }
    __syncthreads();

    if (tid < OUTC) {
        float acc = b2[tid] + shalf[0][tid] + shalf[1][tid];
        float keepf = (float)g_keep[k];
        if (tid < 4) out[KSEL*80 + k*4 + tid] = (g_rois[k*4 + tid] + acc) * keepf;
        else         out[(size_t)k*80 + (tid - 4)] = acc * keepf;
    }
    if (tid == 255) out[KSEL*80 + KSEL*4 + k] = (float)g_keep[k];
}

// ---------------- launch ----------------------------------------------------
extern "C" void kernel_launch(void* const* d_in, const int* in_sizes, int n_in,
                              void* d_out, int out_size) {
    const float* pred    = (const float*)d_in[0];
    const float* rois    = (const float*)d_in[1];
    const float* anchors = (const float*)d_in[2];
    const int*   assign  = (const int*)  d_in[3];
    const float* feats   = (const float*)d_in[4];
    const float* W1      = (const float*)d_in[5];
    const float* b1      = (const float*)d_in[6];
    const float* gamma   = (const float*)d_in[7];
    const float* beta    = (const float*)d_in[8];
    const float* mm      = (const float*)d_in[9];
    const float* mv      = (const float*)d_in[10];
    const float* W2      = (const float*)d_in[11];
    const float* b2      = (const float*)d_in[12];
    float* out = (float*)d_out;

    k_filtersel<<<NTOT/1024, 1024>>>(pred, rois, anchors, assign, W2);
    k_gatherall<<<dim3(KSEL, NQ), 256>>>(feats);
    k_gemm1a<<<dim3(NGRP, NKC), 256>>>(W1);
    k_tail<<<KSEL, 256>>>(b1, gamma, beta, mm, mv, b2, out);
}

// round 17
// speedup vs baseline: 1.2852x; 1.1606x over previous
#include <cuda_runtime.h>
#include <stdint.h>

#define NTOT  (8*32*32*9)   // 73728
#define KSEL  512
#define HF_   32
#define WF_   32
#define CCH   1024
#define FEAT  256
#define OUTC  84
#define SS_   14
#define NSAMP 196
#define DET_THRC 0.7f
#define NMS_IOUC 0.7f
#define NBINS 4096
#define NKC   8                 // K chunks in gemm1 (128 c each)
#define GRP   16                // rois per gemm1 group
#define NGRP  (KSEL/GRP)        // 32

typedef unsigned long long ull;

// ---------------- device scratch (static globals; zero-initialized) ---------
__device__ uint64_t g_cand[NTOT];
__device__ int      g_cand_count;                 // reset by k_select
__device__ __align__(16) int g_hist[NBINS];       // reset by k_select
__device__ int      g_valid[KSEL];
__device__ int      g_assign[KSEL];
__device__ float    g_rois[KSEL*4];
__device__ float    g_shifted[KSEL*4];
__device__ unsigned g_sup[KSEL*16];
__device__ unsigned g_supany[16];                 // reset by resolver
__device__ int      g_keep[KSEL];
__device__ int      g_done;                       // reset by resolver
__device__ int      g_cnt[KSEL];
__device__ int      g_plist[KSEL*128];
__device__ float    g_wlist[KSEL*128];
__device__ __align__(16) float g_W2T[OUTC*FEAT];        // W2 transposed [o][c]
__device__ __align__(16) float g_poolT[KSEL*CCH];       // [grp=k/16][c][k%16]
__device__ __align__(16) float g_part[NKC*KSEL*FEAT];   // [kc][roi][col]

// ---------------- filter: score > 0.7 -> key + hist; also W2 transpose ------
__global__ void k_filter(const float* __restrict__ pred,
                         const float* __restrict__ W2) {
    int i = blockIdx.x * blockDim.x + threadIdx.x;
    float s = (i < NTOT) ? pred[i] : 0.0f;
    bool c = (s > DET_THRC);
    unsigned m = __ballot_sync(0xffffffffu, c);
    int n = __popc(m);
    int base = 0;
    if ((threadIdx.x & 31) == 0 && n)
        base = atomicAdd(&g_cand_count, n);
    base = __shfl_sync(0xffffffffu, base, 0);
    if (c) {
        int r = __popc(m & ((1u << (threadIdx.x & 31)) - 1u));
        unsigned u = __float_as_uint(s); // s > 0 -> monotone as unsigned
        g_cand[base + r] = ((uint64_t)u << 32) | (unsigned)(0xFFFFFFFFu - (unsigned)i);
        atomicAdd(&g_hist[u >> 19], 1);
    }
    // W2 transpose for the tail (each element written exactly once)
    if (i < OUTC * FEAT) {
        int o  = i >> 8;
        int cc = i & 255;
        g_W2T[o * 256 + cc] = W2[cc * OUTC + o];
    }
}

// ------- single-block: histogram cutoff + 1-pass collect + hybrid bitonic ---
__global__ void __launch_bounds__(1024) k_select(const float* __restrict__ rois,
                                                 const float* __restrict__ anchors,
                                                 const int*   __restrict__ assign) {
    __shared__ int      sh_hist[NBINS];
    __shared__ int      sh_chunk[1024];
    __shared__ int      sh_warp[32];
    __shared__ unsigned sh_T;
    __shared__ int      sh_cnt;
    __shared__ uint64_t sh_keys[1024];
    int tid = threadIdx.x;
    int lane = tid & 31, wid = tid >> 5;

    int M = g_cand_count; if (M > NTOT) M = NTOT;
    __syncthreads();
    if (tid == 0) { g_cand_count = 0; sh_cnt = 0; }

    int4 h = ((const int4*)g_hist)[tid];
    ((int4*)g_hist)[tid] = make_int4(0, 0, 0, 0);
    sh_hist[tid*4+0] = h.x; sh_hist[tid*4+1] = h.y;
    sh_hist[tid*4+2] = h.z; sh_hist[tid*4+3] = h.w;
    int csum = h.x + h.y + h.z + h.w;
    sh_chunk[tid] = csum;
    int ws = csum;
    #pragma unroll
    for (int off = 16; off > 0; off >>= 1) ws += __shfl_down_sync(0xffffffffu, ws, off);
    if (lane == 0) sh_warp[wid] = ws;
    __syncthreads();

    if (tid == 0) {
        unsigned T = 1u;
        int cum = 0; int w;
        bool found = false;
        for (w = 31; w >= 0; w--) {
            if (cum + sh_warp[w] >= KSEL) { found = true; break; }
            cum += sh_warp[w];
        }
        if (found) {
            int c;
            for (c = 31; c >= 0; c--) {
                int t = sh_chunk[w*32 + c];
                if (cum + t >= KSEL) break;
                cum += t;
            }
            int base = (w*32 + c) * 4;
            int b;
            for (b = 3; b >= 0; b--) {
                int t = sh_hist[base + b];
                if (cum + t >= KSEL) break;
                cum += t;
            }
            T = (unsigned)(base + b) << 19;
        }
        sh_T = T;
    }
    __syncthreads();
    unsigned T = sh_T;

    for (int j = tid; j < M; j += 1024) {
        uint64_t k = g_cand[j];
        if ((unsigned)(k >> 32) >= T) {
            int p = atomicAdd(&sh_cnt, 1);
            if (p < 1024) sh_keys[p] = k;
        }
    }
    __syncthreads();
    int cnt = sh_cnt; if (cnt > 1024) cnt = 1024;
    if (tid >= cnt) sh_keys[tid] = 0ull;
    __syncthreads();

    // hybrid bitonic sort (descending)
    uint64_t v = sh_keys[tid];
    #pragma unroll
    for (int size = 2; size <= 32; size <<= 1) {
        #pragma unroll
        for (int stride = size >> 1; stride >= 1; stride >>= 1) {
            uint64_t o = __shfl_xor_sync(0xffffffffu, v, stride);
            bool lower = (tid & stride) == 0;
            bool desc  = (tid & size) == 0;
            uint64_t mx = v > o ? v : o, mn = v > o ? o : v;
            v = (desc == lower) ? mx : mn;
        }
    }
    sh_keys[tid] = v;
    __syncthreads();
    for (int size = 64; size <= 1024; size <<= 1) {
        for (int stride = size >> 1; stride >= 32; stride >>= 1) {
            int j = tid ^ stride;
            if (j > tid) {
                uint64_t a = sh_keys[tid], b = sh_keys[j];
                bool desc = (tid & size) == 0;
                if (desc ? (a < b) : (a > b)) { sh_keys[tid] = b; sh_keys[j] = a; }
            }
            __syncthreads();
        }
        v = sh_keys[tid];
        #pragma unroll
        for (int stride = 16; stride >= 1; stride >>= 1) {
            uint64_t o = __shfl_xor_sync(0xffffffffu, v, stride);
            bool lower = (tid & stride) == 0;
            bool desc  = (tid & size) == 0;
            uint64_t mx = v > o ? v : o, mn = v > o ? o : v;
            v = (desc == lower) ? mx : mn;
        }
        sh_keys[tid] = v;
        __syncthreads();
    }

    if (tid < KSEL) {
        uint64_t k = sh_keys[tid];
        unsigned u = (unsigned)(k >> 32);
        int idx = 0, vv = 0;
        if (u != 0u) { idx = (int)(0xFFFFFFFFu - (unsigned)(k & 0xFFFFFFFFu)); vv = 1; }
        g_valid[tid] = vv;
        int a = assign[idx];
        g_assign[tid] = a;
        float fa = (float)a * 1024.0f;
        #pragma unroll
        for (int c = 0; c < 4; c++) g_rois[tid*4 + c] = rois[idx*4 + c];
        float cy = anchors[idx*4+0], cx = anchors[idx*4+1];
        float hh = anchors[idx*4+2], ww = anchors[idx*4+3];
        g_shifted[tid*4+0] = cy - hh*0.5f + fa;
        g_shifted[tid*4+1] = cx - ww*0.5f + fa;
        g_shifted[tid*4+2] = cy + hh*0.5f + fa;
        g_shifted[tid*4+3] = cx + ww*0.5f + fa;
    }
}

// === 512 blocks: roi weight-list prep + per-roi NMS sup; last block resolves
__global__ void __launch_bounds__(256) k_supres() {
    __shared__ float4   sb[KSEL];
    __shared__ float    wmap[1024];
    __shared__ int      plist[128];
    __shared__ float    wlist[128];
    __shared__ int      cnt;
    __shared__ int      s_last;
    int k   = blockIdx.x;
    int tid = threadIdx.x;

    const float4* gs = (const float4*)g_shifted;
    #pragma unroll
    for (int i = tid; i < KSEL; i += 256) sb[i] = gs[i];
    for (int i = tid; i < 1024; i += 256) wmap[i] = 0.0f;
    if (tid == 0) cnt = 0;
    __syncthreads();

    if (tid < 16) {
        float4 bi = sb[k];
        float ai = (bi.z - bi.x) * (bi.w - bi.y);
        unsigned bits = 0u;
        #pragma unroll 8
        for (int b = 0; b < 32; b++) {
            int j = tid*32 + b;
            if (j > k) {
                float4 bj = sb[j];
                float yA = fmaxf(bi.x, bj.x), xA = fmaxf(bi.y, bj.y);
                float yB = fminf(bi.z, bj.z), xB = fminf(bi.w, bj.w);
                float inter = fmaxf(yB - yA, 0.0f) * fmaxf(xB - xA, 0.0f);
                float aj = (bj.z - bj.x) * (bj.w - bj.y);
                if (inter > NMS_IOUC * (ai + aj - inter + 1e-8f)) bits |= (1u << b);
            }
        }
        g_sup[k*16 + tid] = bits;
        if (bits) atomicOr(&g_supany[k >> 5], 1u << (k & 31));
    }

    if (tid < NSAMP) {
        const float sc = 32.0f / 1024.0f;
        float ry1 = g_rois[k*4+0] * sc, rx1 = g_rois[k*4+1] * sc;
        float ry2 = g_rois[k*4+2] * sc, rx2 = g_rois[k*4+3] * sc;
        int sy = tid / SS_, sx = tid % SS_;
        float fy = ((float)sy + 0.5f) / (float)SS_;
        float fx = ((float)sx + 0.5f) / (float)SS_;
        float yy = ry1 + fy * (ry2 - ry1) - 0.5f;
        float xx = rx1 + fx * (rx2 - rx1) - 0.5f;
        float yc = fminf(fmaxf(yy, 0.0f), 31.0f);
        float xc = fminf(fmaxf(xx, 0.0f), 31.0f);
        float y0 = floorf(yc), x0 = floorf(xc);
        float wy = yc - y0,  wx = xc - x0;
        int y0i = (int)y0, x0i = (int)x0;
        int y1i = min(y0i + 1, 31), x1i = min(x0i + 1, 31);
        atomicAdd(&wmap[y0i*32 + x0i], (1.0f - wy) * (1.0f - wx));
        atomicAdd(&wmap[y0i*32 + x1i], (1.0f - wy) * wx);
        atomicAdd(&wmap[y1i*32 + x0i], wy * (1.0f - wx));
        atomicAdd(&wmap[y1i*32 + x1i], wy * wx);
    }
    __syncthreads();
    for (int p = tid; p < 1024; p += 256) {
        float w = wmap[p];
        if (w != 0.0f) {
            int pos = atomicAdd(&cnt, 1);
            plist[pos] = p; wlist[pos] = w;
        }
    }
    __syncthreads();
    int n = cnt;
    if (tid == 0) g_cnt[k] = n;
    if (tid < n) { g_plist[k*128 + tid] = plist[tid]; g_wlist[k*128 + tid] = wlist[tid]; }

    __threadfence();
    __syncthreads();
    if (tid == 0) s_last = (atomicAdd(&g_done, 1) == KSEL - 1) ? 1 : 0;
    __syncthreads();
    if (!s_last) return;

    __shared__ unsigned ssup[KSEL*16];
    __shared__ unsigned sany[16];
    __shared__ unsigned sword[16];
    __threadfence();
    #pragma unroll
    for (int i = tid; i < KSEL*16; i += 256) ssup[i] = g_sup[i];
    #pragma unroll
    for (int q = 0; q < 2; q++) {
        int i = q*256 + tid;
        int v = g_valid[i];
        unsigned bm = __ballot_sync(0xffffffffu, v != 0);
        if ((i & 31) == 0) sword[i >> 5] = bm;
    }
    if (tid < 16) { sany[tid] = g_supany[tid]; g_supany[tid] = 0u; }
    if (tid == 0) g_done = 0;
    __syncthreads();

    if (tid < 32) {
        unsigned word = (tid < 16) ? sword[tid] : 0u;
        for (int ww = 0; ww < 16; ww++) {
            unsigned anyw = sany[ww];
            if (!anyw) continue;
            for (int b = 0; b < 32; b++) {
                if (!((anyw >> b) & 1u)) continue;
                int ii = ww*32 + b;
                unsigned wi = __shfl_sync(0xffffffffu, word, ww);
                if ((wi >> b) & 1u) {
                    if (tid < 16) word &= ~ssup[ii*16 + tid];
                }
            }
        }
        if (tid < 16) sword[tid] = word;
    }
    __syncthreads();
    #pragma unroll
    for (int q = 0; q < 2; q++) {
        int i = q*256 + tid;
        g_keep[i] = (int)((sword[i >> 5] >> (i & 31)) & 1u);
    }
}

// ------- gather: (roi, channel-half) = 1024 blocks x 128 thr, MLP-8 ---------
__global__ void __launch_bounds__(128) k_gather(const float* __restrict__ feats) {
    __shared__ int   spl[128];
    __shared__ float swl[128];
    __shared__ int   scnt;
    __shared__ int   sas;
    int k   = blockIdx.x;
    int h   = blockIdx.y;
    int tid = threadIdx.x;
    if (tid == 0) { scnt = g_cnt[k]; sas = g_assign[k]; }
    spl[tid] = g_plist[k*128 + tid];
    swl[tid] = g_wlist[k*128 + tid];
    __syncthreads();

    int n = scnt;
    const float4* fb = (const float4*)(feats + (size_t)sas * (HF_*WF_*CCH)) + h*128 + tid;
    float ax = 0.f, ay = 0.f, az = 0.f, aw = 0.f;
    #pragma unroll 8
    for (int e = 0; e < n; e++) {
        int   p = spl[e];
        float w = swl[e];
        float4 vv = fb[(size_t)p * 256];
        ax += w * vv.x; ay += w * vv.y; az += w * vv.z; aw += w * vv.w;
    }
    const float inv = 1.0f / 196.0f;
    float* po = g_poolT + (size_t)(k >> 4) * (CCH*GRP) + (k & 15);
    int c0 = (h*128 + tid) * 4;
    po[(size_t)(c0+0)*GRP] = ax * inv;
    po[(size_t)(c0+1)*GRP] = ay * inv;
    po[(size_t)(c0+2)*GRP] = az * inv;
    po[(size_t)(c0+3)*GRP] = aw * inv;
}

// ------- GEMM1a: (32 groups of 16 rois, 8 K-chunks of 128) x 256, MLP-8 -----
__global__ void __launch_bounds__(256) k_gemm1a(const float* __restrict__ W1) {
    __shared__ __align__(16) float sp[128*GRP];   // [c in chunk][16 rois] 8KB
    int g   = blockIdx.x;
    int kc  = blockIdx.y;
    int tid = threadIdx.x;   // output col

    const float4* src = (const float4*)(g_poolT + (size_t)g * (CCH*GRP) + kc * (128*GRP));
    float4* dst = (float4*)sp;
    #pragma unroll
    for (int i = tid; i < 128*GRP/4; i += 256) dst[i] = src[i];
    __syncthreads();

    const float* w1 = W1 + (size_t)(kc * 128) * 256 + tid;
    ull a[8];
    #pragma unroll
    for (int j = 0; j < 8; j++) a[j] = 0ull;
    const ull* spu = (const ull*)sp;

    for (int c0 = 0; c0 < 128; c0 += 8) {
        float w[8];
        #pragma unroll
        for (int j = 0; j < 8; j++) w[j] = w1[(size_t)(c0 + j) * 256];  // 8 LDGs in flight
        #pragma unroll
        for (int j = 0; j < 8; j++) {
            ull w2;
            asm("mov.b64 %0, {%1, %1};" : "=l"(w2) : "r"(__float_as_uint(w[j])));
            #pragma unroll
            for (int jj = 0; jj < 8; jj++)
                asm("fma.rn.f32x2 %0, %1, %2, %0;" : "+l"(a[jj]) : "l"(spu[(c0+j)*8 + jj]), "l"(w2));
        }
    }

    float* pp = g_part + (size_t)kc * (KSEL*FEAT) + (size_t)(g * GRP) * 256 + tid;
    #pragma unroll
    for (int j = 0; j < 8; j++) {
        unsigned lo, hi;
        asm("mov.b64 {%0, %1}, %2;" : "=r"(lo), "=r"(hi) : "l"(a[j]));
        pp[(size_t)(2*j  ) * 256] = __uint_as_float(lo);
        pp[(size_t)(2*j+1) * 256] = __uint_as_float(hi);
    }
}

// ====== tail: 1 roi/block, 512 x 256; NKC=8 reduce + W2T float4 GEMM2 =======
__global__ void __launch_bounds__(256) k_tail(const float* __restrict__ b1,
                                              const float* __restrict__ gamma,
                                              const float* __restrict__ beta,
                                              const float* __restrict__ mm,
                                              const float* __restrict__ mv,
                                              const float* __restrict__ b2,
                                              float* __restrict__ out) {
    __shared__ __align__(16) float sh[FEAT];
    __shared__ float shalf[2][OUTC];
    int k   = blockIdx.x;
    int tid = threadIdx.x;

    {
        const float* pp = g_part + (size_t)k * 256 + tid;
        float s = 0.0f;
        #pragma unroll
        for (int kc = 0; kc < NKC; kc++) s += pp[(size_t)kc * (KSEL*FEAT)];
        float hv = (s + b1[tid] - mm[tid]) * rsqrtf(mv[tid] + 1e-3f) * gamma[tid] + beta[tid];
        sh[tid] = fmaxf(hv, 0.0f);
    }
    __syncthreads();

    if (tid < 2*OUTC) {
        int o  = tid >> 1;
        int hf = tid & 1;
        const float4* w4 = (const float4*)g_W2T + o*64 + hf*32;
        const float4* h4 = (const float4*)sh + hf*32;
        float acc = 0.0f;
        #pragma unroll 8
        for (int c = 0; c < 32; c++) {
            float4 w = w4[c], hh = h4[c];
            acc += w.x*hh.x + w.y*hh.y + w.z*hh.z + w.w*hh.w;
        }
        shalf[hf][o] = acc;
    }
    __syncthreads();

    if (tid < OUTC) {
        float acc = b2[tid] + shalf[0][tid] + shalf[1][tid];
        float keepf = (float)g_keep[k];
        if (tid < 4) out[KSEL*80 + k*4 + tid] = (g_rois[k*4 + tid] + acc) * keepf;
        else         out[(size_t)k*80 + (tid - 4)] = acc * keepf;
    }
    if (tid == 255) out[KSEL*80 + KSEL*4 + k] = (float)g_keep[k];
}

// ---------------- launch ----------------------------------------------------
extern "C" void kernel_launch(void* const* d_in, const int* in_sizes, int n_in,
                              void* d_out, int out_size) {
    const float* pred    = (const float*)d_in[0];
    const float* rois    = (const float*)d_in[1];
    const float* anchors = (const float*)d_in[2];
    const int*   assign  = (const int*)  d_in[3];
    const float* feats   = (const float*)d_in[4];
    const float* W1      = (const float*)d_in[5];
    const float* b1      = (const float*)d_in[6];
    const float* gamma   = (const float*)d_in[7];
    const float* beta    = (const float*)d_in[8];
    const float* mm      = (const float*)d_in[9];
    const float* mv      = (const float*)d_in[10];
    const float* W2      = (const float*)d_in[11];
    const float* b2      = (const float*)d_in[12];
    float* out = (float*)d_out;

    k_filter<<<(NTOT + 255) / 256, 256>>>(pred, W2);
    k_select<<<1, 1024>>>(rois, anchors, assign);
    k_supres<<<KSEL, 256>>>();
    k_gather<<<dim3(KSEL, 2), 128>>>(feats);
    k_gemm1a<<<dim3(NGRP, NKC), 256>>>(W1);
    k_tail<<<KSEL, 256>>>(b1, gamma, beta, mm, mv, b2, out);
}